// round 16
// baseline (speedup 1.0000x reference)
#include <cuda_runtime.h>
#include <cuda_fp16.h>
#include <cstdint>

#define MAXQ 4096
#define TPB 256

// Packed per-query params
static __device__ float4 g_px[MAXQ];   // (c0, c1, c2, Ix as float bits) for x-stage
static __device__ int    g_Iy[MAXQ];
static __device__ float4 g_dy[MAXQ];   // (h0, h1, h2, h3*r) for y-stage

// Multi-block precompute: axis staged in smem, binary search in smem.
__global__ void precompute_kernel(const float* __restrict__ xaxis,
                                  const float* __restrict__ yaxis,
                                  const float* __restrict__ xs,
                                  const float* __restrict__ ys,
                                  int N) {
    extern __shared__ float ax[];
    bool is_y = (blockIdx.y != 0);
    const float* axis = is_y ? yaxis : xaxis;
    const float* qs   = is_y ? ys    : xs;
    for (int i = threadIdx.x; i < N; i += blockDim.x)
        ax[i] = axis[i];
    __syncthreads();

    int q = blockIdx.x * blockDim.x + threadIdx.x;
    if (q >= N) return;
    float v = qs[q];
    // Exact replica of jnp.searchsorted(axis[1:-1], v, side='left')
    int lo = 0, hi = N - 2;
    while (lo < hi) {
        int mid = (lo + hi) >> 1;
        if (ax[1 + mid] < v) lo = mid + 1; else hi = mid;
    }
    int I = lo;
    float x0 = ax[I], x1 = ax[I + 1], x2 = ax[I + 2];
    float dx = x1 - x0;
    float t = (v - x0) / dx;
    float t2 = t * t, t3 = t2 * t;
    float h0 = 1.0f - 3.0f * t2 + 2.0f * t3;
    float h1 = t - 2.0f * t2 + t3;
    float h2 = 3.0f * t2 - 2.0f * t3;
    float h3 = t3 - t2;
    float r = dx / (x2 - x1);
    if (!is_y) {
        g_px[q] = make_float4(h0 - h1, h1 + h2 - h3 * r, h3 * r, __int_as_float(I));
    } else {
        g_Iy[q] = I;
        g_dy[q] = make_float4(h0, h1, h2, h3 * r);
    }
}

__device__ __forceinline__ uint2 pack_half4(float w0, float w1, float w2, float w3) {
    __half2 h01 = __floats2half2_rn(w0, w1);
    __half2 h23 = __floats2half2_rn(w2, w3);
    return make_uint2(*reinterpret_cast<uint32_t*>(&h01),
                      *reinterpret_cast<uint32_t*>(&h23));
}

// One compute iteration: 3 random LDS.64 taps + 4 coalesced STG.
__device__ __forceinline__ void compute_iter(const uint2* __restrict__ w, int q, float4 p,
                                             const float* colt,
                                             float* __restrict__ obase, size_t pstride) {
    int I = __float_as_int(p.w);
    uint2 ua = w[I];
    uint2 ub = w[I + 1];
    uint2 uc = w[I + 2];
    float2 a01 = __half22float2(*reinterpret_cast<__half2*>(&ua.x));
    float2 a23 = __half22float2(*reinterpret_cast<__half2*>(&ua.y));
    float2 b01 = __half22float2(*reinterpret_cast<__half2*>(&ub.x));
    float2 b23 = __half22float2(*reinterpret_cast<__half2*>(&ub.y));
    float2 c01 = __half22float2(*reinterpret_cast<__half2*>(&uc.x));
    float2 c23 = __half22float2(*reinterpret_cast<__half2*>(&uc.y));
    obase[0 * pstride + q] = p.x * a01.x + p.y * b01.x + p.z * c01.x + colt[0];
    obase[1 * pstride + q] = p.x * a01.y + p.y * b01.y + p.z * c01.y + colt[1];
    obase[2 * pstride + q] = p.x * a23.x + p.y * b23.x + p.z * c23.x + colt[2];
    obase[3 * pstride + q] = p.x * a23.y + p.y * b23.y + p.z * c23.y + colt[3];
}

// One fill iteration: 12 coalesced LDG, colt fp32-exact, half4 w to smem.
__device__ __forceinline__ void fill_iter(const float* __restrict__ rbase, size_t pstride,
                                          int N, int q, float4 d,
                                          float* colt, uint2* __restrict__ wdst) {
    float wv[4];
#pragma unroll
    for (int k = 0; k < 4; ++k) {
        const float* __restrict__ rk = rbase + (size_t)k * pstride;
        float a  = __ldg(rk + q);
        float b  = __ldg(rk + N + q);
        float s2 = __ldg(rk + 2 * N + q);
        colt[k] = d.y * (b - a) + d.w * (s2 - b);
        wv[k] = d.x * a + d.z * b;
    }
    wdst[q] = pack_half4(wv[0], wv[1], wv[2], wv[3]);
}

// Two-row pipelined 4-batch kernel (N==1024, 512 thr).
// fillA | bar | {issue B LDGs -> computeA (LDS-bound) -> consume B} | bar | computeB
// x-params are row-independent: loaded once, reused for both rows (8 output rows total).
__global__ __launch_bounds__(512, 3) void fused4h_pipe_kernel(const float* __restrict__ signal,
                                                              float* __restrict__ out,
                                                              int N) {
    extern __shared__ uint2 w8[];      // 2*N entries: [wA | wB]
    uint2* wA = w8;
    uint2* wB = w8 + N;
    int half = N >> 1;
    int bq = blockIdx.x / half;
    int ry = blockIdx.x - bq * half;
    int qyA = ry * 2, qyB = ry * 2 + 1;
    size_t pstride = (size_t)N * N;
    const float* __restrict__ base = signal + (size_t)(bq * 4) * pstride;
    float* __restrict__ obb = out + (size_t)(bq * 4) * pstride;

    int q0 = threadIdx.x;
    int q1 = threadIdx.x + 512;

    // ---- fill row A ----
    int IyA = g_Iy[qyA];
    float4 dA = g_dy[qyA];
    const float* __restrict__ rA = base + (size_t)IyA * N;
    float* __restrict__ oA = obb + (size_t)qyA * N;
    float coltA0[4], coltA1[4];
    fill_iter(rA, pstride, N, q0, dA, coltA0, wA);
    fill_iter(rA, pstride, N, q1, dA, coltA1, wA);

    // prefetch params across the barrier (row-independent, reused for row B)
    float4 p0 = g_px[q0];
    __syncthreads();
    float4 p1 = g_px[q1];

    // ---- middle: compute A while filling B ----
    int IyB = g_Iy[qyB];
    float4 dB = g_dy[qyB];
    const float* __restrict__ rB = base + (size_t)IyB * N;
    float* __restrict__ oB = obb + (size_t)qyB * N;
    float coltB0[4], coltB1[4];

    {   // B iter0 loads issued first; compute A iter0 covers their latency
        float a[4], b[4], s[4];
#pragma unroll
        for (int k = 0; k < 4; ++k) {
            const float* __restrict__ rk = rB + (size_t)k * pstride;
            a[k] = __ldg(rk + q0); b[k] = __ldg(rk + N + q0); s[k] = __ldg(rk + 2 * N + q0);
        }
        compute_iter(wA, q0, p0, coltA0, oA, pstride);
        float wv[4];
#pragma unroll
        for (int k = 0; k < 4; ++k) {
            coltB0[k] = dB.y * (b[k] - a[k]) + dB.w * (s[k] - b[k]);
            wv[k] = dB.x * a[k] + dB.z * b[k];
        }
        wB[q0] = pack_half4(wv[0], wv[1], wv[2], wv[3]);
    }
    {   // B iter1 loads; compute A iter1 covers them
        float a[4], b[4], s[4];
#pragma unroll
        for (int k = 0; k < 4; ++k) {
            const float* __restrict__ rk = rB + (size_t)k * pstride;
            a[k] = __ldg(rk + q1); b[k] = __ldg(rk + N + q1); s[k] = __ldg(rk + 2 * N + q1);
        }
        compute_iter(wA, q1, p1, coltA1, oA, pstride);
        float wv[4];
#pragma unroll
        for (int k = 0; k < 4; ++k) {
            coltB1[k] = dB.y * (b[k] - a[k]) + dB.w * (s[k] - b[k]);
            wv[k] = dB.x * a[k] + dB.z * b[k];
        }
        wB[q1] = pack_half4(wv[0], wv[1], wv[2], wv[3]);
    }
    __syncthreads();

    // ---- compute row B (params already resident) ----
    compute_iter(wB, q0, p0, coltB0, oB, pstride);
    compute_iter(wB, q1, p1, coltB1, oB, pstride);
}

// Generic single-batch fallback
__global__ __launch_bounds__(TPB) void fused_kernel_gen(const float* __restrict__ signal,
                                                        float* __restrict__ out,
                                                        int N) {
    extern __shared__ float w[];
    int b  = blockIdx.x / N;
    int qy = blockIdx.x - b * N;
    int Iy = g_Iy[qy];
    float4 d = g_dy[qy];
    size_t plane = (size_t)b * N * N;
    const float* __restrict__ r0 = signal + plane + (size_t)Iy * N;
    const float* __restrict__ r1 = r0 + N;
    const float* __restrict__ r2 = r1 + N;
    float* __restrict__ orow = out + plane + (size_t)qy * N;

    for (int q = threadIdx.x; q < N; q += TPB)
        w[q] = d.x * __ldg(r0 + q) + d.z * __ldg(r1 + q);
    __syncthreads();
    for (int q = threadIdx.x; q < N; q += TPB) {
        float4 p = g_px[q];
        int I = __float_as_int(p.w);
        float g = p.x * w[I] + p.y * w[I + 1] + p.z * w[I + 2];
        float a = __ldg(r0 + q), bb = __ldg(r1 + q), s2 = __ldg(r2 + q);
        orow[q] = g + d.y * (bb - a) + d.w * (s2 - bb);
    }
}

extern "C" void kernel_launch(void* const* d_in, const int* in_sizes, int n_in,
                              void* d_out, int out_size) {
    const float* xaxis  = (const float*)d_in[0];
    const float* yaxis  = (const float*)d_in[1];
    const float* signal = (const float*)d_in[2];
    const float* xs     = (const float*)d_in[3];
    const float* ys     = (const float*)d_in[4];
    float* out = (float*)d_out;

    int N = in_sizes[0];                       // 1024
    int B = (int)((long long)in_sizes[2] / ((long long)N * N));  // 32

    dim3 pg((N + TPB - 1) / TPB, 2);
    precompute_kernel<<<pg, TPB, N * sizeof(float)>>>(xaxis, yaxis, xs, ys, N);

    if ((B % 4) == 0 && N == 1024) {
        fused4h_pipe_kernel<<<(B / 4) * (N / 2), 512, 2 * N * sizeof(uint2)>>>(signal, out, N);
    } else {
        fused_kernel_gen<<<B * N, TPB, N * sizeof(float)>>>(signal, out, N);
    }
}